// round 3
// baseline (speedup 1.0000x reference)
#include <cuda_runtime.h>
#include <cstdint>

#define NN 50000
#define NE 800000
#define DH 96
#define DE 16

typedef unsigned long long ull;
typedef long long ll;

// ---------------- scratch: __device__ globals (no allocs allowed) ------------
__device__ float g_X[NN * DH];
__device__ float g_U[NN * DH];
__device__ float g_AGG[NN * DH];
__device__ float g_H[NN * DH];
__device__ float g_GI[NN * 3 * DH];
__device__ float g_GH[NN * 3 * DH];
__device__ float g_AD[NN];
__device__ float g_AS[NN];
__device__ int g_src[NE];
__device__ int g_dst[NE];
__device__ int g_deg[NN];
__device__ int g_rowp[NN + 1];
__device__ int g_cur[NN];
__device__ int g_bsum[64];
__device__ int g_is64;
__device__ int g_csr_src[NE];
__device__ int g_csr_eid[NE];

// ---------------- helpers ----------------------------------------------------
__device__ __forceinline__ void ffma2(ull &acc, ull a, ull w) {
    asm("fma.rn.f32x2 %0, %1, %2, %0;" : "+l"(acc) : "l"(a), "l"(w));
}
__device__ __forceinline__ ull pack2(float a) {
    ull r;
    unsigned ai = __float_as_uint(a);
    asm("mov.b64 %0, {%1, %1};" : "=l"(r) : "r"(ai));
    return r;
}
__device__ __forceinline__ float leakyf(float v) { return v >= 0.f ? v : 0.01f * v; }
__device__ __forceinline__ float eluf(float v) { return v > 0.f ? v : expm1f(v); }
__device__ __forceinline__ float sigmf(float v) { return 1.f / (1.f + __expf(-v)); }

// ---------------- edge_index dtype detection + extraction --------------------
// If the harness stored edge_index as int64, the first 64 values (row 0 = src)
// interpreted as int64 all lie in [0, NN). If stored as int32, reading pairs as
// int64 packs two node ids -> values >= 2^32 almost surely. Only reads the
// first 512 bytes, valid under both layouts.
__global__ void k_detect(const void *__restrict__ ei) {
    if (threadIdx.x == 0 && blockIdx.x == 0) {
        const ll *e64 = (const ll *)ei;
        int ok = 1;
        for (int i = 0; i < 64; i++) {
            ll v = e64[i];
            if (v < 0 || v >= NN) { ok = 0; break; }
        }
        g_is64 = ok;
    }
}

__global__ void k_extract(const void *__restrict__ ei) {
    int i = blockIdx.x * blockDim.x + threadIdx.x;
    if (i >= NE) return;
    if (g_is64) {
        const ll *e64 = (const ll *)ei;
        g_src[i] = (int)e64[i];
        g_dst[i] = (int)e64[NE + i];
    } else {
        const int *e32 = (const int *)ei;
        g_src[i] = e32[i];
        g_dst[i] = e32[NE + i];
    }
}

// ---------------- CSR build --------------------------------------------------
__global__ void k_zero_deg() {
    int i = blockIdx.x * blockDim.x + threadIdx.x;
    if (i < NN) g_deg[i] = 0;
}

__global__ void k_hist() {
    int i = blockIdx.x * blockDim.x + threadIdx.x;
    if (i < NE) atomicAdd(&g_deg[g_dst[i]], 1);
}

__global__ void k_bsum() {
    __shared__ int sred[32];
    int tid = threadIdx.x;
    int i = blockIdx.x * 1024 + tid;
    int v = (i < NN) ? g_deg[i] : 0;
#pragma unroll
    for (int off = 16; off > 0; off >>= 1) v += __shfl_xor_sync(0xffffffffu, v, off);
    if ((tid & 31) == 0) sred[tid >> 5] = v;
    __syncthreads();
    if (tid < 32) {
        int t = sred[tid];
#pragma unroll
        for (int off = 16; off > 0; off >>= 1) t += __shfl_xor_sync(0xffffffffu, t, off);
        if (tid == 0) g_bsum[blockIdx.x] = t;
    }
}

__global__ void k_bscan() {
    if (threadIdx.x == 0 && blockIdx.x == 0) {
        int s = 0;
        for (int b = 0; b < 49; b++) {
            int t = g_bsum[b];
            g_bsum[b] = s;
            s += t;
        }
        g_rowp[0] = 0;
    }
}

__global__ void k_scan() {
    __shared__ int sb[1024];
    int tid = threadIdx.x;
    int i = blockIdx.x * 1024 + tid;
    int v = (i < NN) ? g_deg[i] : 0;
    sb[tid] = v;
    __syncthreads();
    for (int off = 1; off < 1024; off <<= 1) {
        int t = (tid >= off) ? sb[tid - off] : 0;
        __syncthreads();
        sb[tid] += t;
        __syncthreads();
    }
    if (i < NN) {
        int incl = sb[tid] + g_bsum[blockIdx.x];
        g_rowp[i + 1] = incl;
        g_cur[i] = incl - v;
    }
}

__global__ void k_scatter() {
    int i = blockIdx.x * blockDim.x + threadIdx.x;
    if (i < NE) {
        int d = g_dst[i];
        int p = atomicAdd(&g_cur[d], 1);
        g_csr_src[p] = g_src[i];
        g_csr_eid[p] = i;
    }
}

// ---------------- generic GEMM: C[nrows,Mfull] = act(A[nrows,K] @ W (+b)) ----
// f32x2 packed FMA. 64-row blocks, 128 threads, 4x12 per-thread tile,
// 96-col tiles via blockIdx.y. WT=true: W stored [Mfull,K] (compute A @ W^T).
#define ACT_NONE 0
#define ACT_BIAS 1
#define ACT_LEAKY 2
#define ACT_ELU 3

template <int K, int ACT, bool WT>
__global__ __launch_bounds__(128) void mm_kernel(const float *__restrict__ A,
                                                 const float *__restrict__ W,
                                                 const float *__restrict__ bias,
                                                 float *__restrict__ C, int nrows,
                                                 int Mfull) {
    constexpr int SWS = 100;     // 96 + pad, keeps 16B alignment for vector loads
    constexpr int SAS = K + 2;   // (4*SAS) % 32 == 8 -> conflict-free scalar loads
    extern __shared__ float sm[];
    float *sW = sm;              // [K][SWS]
    float *sA = sm + K * SWS;    // [64][SAS]
    const int tid = threadIdx.x;
    const int m0 = blockIdx.y * 96;
    const int r0 = blockIdx.x * 64;

    if (!WT) {
        for (int i = tid; i < K * 96; i += 128) {
            int k = i / 96, j = i - k * 96;
            sW[k * SWS + j] = W[(size_t)k * Mfull + m0 + j];
        }
    } else {
        for (int i = tid; i < 96 * K; i += 128) {
            int j = i / K, k = i - j * K;
            sW[k * SWS + j] = W[(size_t)(m0 + j) * K + k];
        }
    }
    for (int i = tid; i < 64 * K; i += 128) {
        int r = i / K, k = i - r * K;
        int row = r0 + r;
        sA[r * SAS + k] = (row < nrows) ? A[(size_t)row * K + k] : 0.f;
    }
    __syncthreads();

    const int ct = tid & 7;    // 8 col-threads * 12 cols = 96
    const int rg = tid >> 3;   // 16 row-groups * 4 rows = 64
    const float *wp = sW + 12 * ct;
    const float *ap = sA + (rg * 4) * SAS;

    ull acc[4][6];
#pragma unroll
    for (int r = 0; r < 4; r++)
#pragma unroll
        for (int q = 0; q < 6; q++) acc[r][q] = 0ull;

#pragma unroll 2
    for (int k = 0; k < K; k++) {
        ulonglong2 wA = *(const ulonglong2 *)(wp + (size_t)k * SWS);
        ulonglong2 wB = *(const ulonglong2 *)(wp + (size_t)k * SWS + 4);
        ulonglong2 wC = *(const ulonglong2 *)(wp + (size_t)k * SWS + 8);
        ull w0 = wA.x, w1 = wA.y, w2 = wB.x, w3 = wB.y, w4 = wC.x, w5 = wC.y;
#pragma unroll
        for (int r = 0; r < 4; r++) {
            ull a2 = pack2(ap[r * SAS + k]);
            ffma2(acc[r][0], a2, w0);
            ffma2(acc[r][1], a2, w1);
            ffma2(acc[r][2], a2, w2);
            ffma2(acc[r][3], a2, w3);
            ffma2(acc[r][4], a2, w4);
            ffma2(acc[r][5], a2, w5);
        }
    }

#pragma unroll
    for (int r = 0; r < 4; r++) {
        int row = r0 + rg * 4 + r;
        if (row >= nrows) break;
        float *cp = C + (size_t)row * Mfull + m0 + 12 * ct;
#pragma unroll
        for (int q = 0; q < 6; q++) {
            float lo = __uint_as_float((unsigned)acc[r][q]);
            float hi = __uint_as_float((unsigned)(acc[r][q] >> 32));
            if (ACT != ACT_NONE) {
                float2 bb = *(const float2 *)(bias + m0 + 12 * ct + 2 * q);
                lo += bb.x;
                hi += bb.y;
                if (ACT == ACT_LEAKY) {
                    lo = leakyf(lo);
                    hi = leakyf(hi);
                } else if (ACT == ACT_ELU) {
                    lo = eluf(lo);
                    hi = eluf(hi);
                }
            }
            *(float2 *)(cp + 2 * q) = make_float2(lo, hi);
        }
    }
}

// ---------------- per-node dot products --------------------------------------
__global__ __launch_bounds__(256) void dots_kernel(const float *__restrict__ X,
                                                   const float *__restrict__ v1,
                                                   const float *__restrict__ v2,
                                                   float *__restrict__ o1,
                                                   float *__restrict__ o2) {
    int lane = threadIdx.x & 31;
    int node = blockIdx.x * 8 + (threadIdx.x >> 5);
    if (node >= NN) return;
    const float *xr = X + (size_t)node * DH;
    float a0 = xr[lane], a1 = xr[lane + 32], a2 = xr[lane + 64];
    float p = a0 * v1[lane] + a1 * v1[lane + 32] + a2 * v1[lane + 64];
#pragma unroll
    for (int off = 16; off > 0; off >>= 1) p += __shfl_xor_sync(0xffffffffu, p, off);
    if (lane == 0) o1[node] = p;
    if (v2) {
        float q = a0 * v2[lane] + a1 * v2[lane + 32] + a2 * v2[lane + 64];
#pragma unroll
        for (int off = 16; off > 0; off >>= 1) q += __shfl_xor_sync(0xffffffffu, q, off);
        if (lane == 0) o2[node] = q;
    }
}

// ---------------- Edge2dConv aggregation (warp per dst, online softmax) ------
__global__ __launch_bounds__(256) void edge0_agg_kernel(
    const float *__restrict__ U, const float *__restrict__ edge_attr,
    const float *__restrict__ We, const float *__restrict__ att_l,
    const float *__restrict__ AD, float *__restrict__ AGG) {
    __shared__ float sWe[DE * DH];
    __shared__ float sAtt[DH];
    int tid = threadIdx.x;
    for (int i = tid; i < DE * DH; i += 256) sWe[i] = We[i];
    if (tid < DH) sAtt[tid] = att_l[tid];
    __syncthreads();

    int lane = tid & 31;
    int node = blockIdx.x * 8 + (tid >> 5);
    if (node >= NN) return;
    int start = g_rowp[node], end = g_rowp[node + 1];
    float adst = AD[node];
    float at0 = sAtt[lane], at1 = sAtt[lane + 32], at2 = sAtt[lane + 64];
    float acc0 = 0.f, acc1 = 0.f, acc2 = 0.f, ssum = 0.f, m = -1e30f;

    for (int p = start; p < end; p++) {
        int s = g_csr_src[p];
        int eid = g_csr_eid[p];
        const float4 *ea4 = (const float4 *)(edge_attr + (size_t)eid * DE);
        float4 E0 = ea4[0], E1 = ea4[1], E2 = ea4[2], E3 = ea4[3];
        float ea[16] = {E0.x, E0.y, E0.z, E0.w, E1.x, E1.y, E1.z, E1.w,
                        E2.x, E2.y, E2.z, E2.w, E3.x, E3.y, E3.z, E3.w};
        float v0 = 0.f, v1 = 0.f, v2 = 0.f;
#pragma unroll
        for (int k = 0; k < 16; k++) {
            v0 = fmaf(ea[k], sWe[k * DH + lane], v0);
            v1 = fmaf(ea[k], sWe[k * DH + lane + 32], v1);
            v2 = fmaf(ea[k], sWe[k * DH + lane + 64], v2);
        }
        const float *ur = U + (size_t)s * DH;
        float mj0 = leakyf(ur[lane] + v0);
        float mj1 = leakyf(ur[lane + 32] + v1);
        float mj2 = leakyf(ur[lane + 64] + v2);
        float part = mj0 * at0 + mj1 * at1 + mj2 * at2;
#pragma unroll
        for (int off = 16; off > 0; off >>= 1)
            part += __shfl_xor_sync(0xffffffffu, part, off);
        float l = leakyf(part + adst);
        float mn = fmaxf(m, l);
        float sc = __expf(m - mn);
        float w = __expf(l - mn);
        acc0 = acc0 * sc + w * mj0;
        acc1 = acc1 * sc + w * mj1;
        acc2 = acc2 * sc + w * mj2;
        ssum = ssum * sc + w;
        m = mn;
    }
    float inv = (end > start) ? 1.f / ssum : 0.f;
    float *og = AGG + (size_t)node * DH;
    og[lane] = acc0 * inv;
    og[lane + 32] = acc1 * inv;
    og[lane + 64] = acc2 * inv;
}

// ---------------- GAT aggregation (warp per dst) + fused bias/elu ------------
__global__ __launch_bounds__(256) void gat_agg_kernel(const float *__restrict__ XW,
                                                      const float *__restrict__ AS,
                                                      const float *__restrict__ AD,
                                                      const float *__restrict__ bias,
                                                      float *__restrict__ H) {
    int lane = threadIdx.x & 31;
    int node = blockIdx.x * 8 + (threadIdx.x >> 5);
    if (node >= NN) return;
    int start = g_rowp[node], end = g_rowp[node + 1];
    float adst = AD[node];
    float acc0 = 0.f, acc1 = 0.f, acc2 = 0.f, ssum = 0.f, m = -1e30f;
    for (int p = start; p < end; p++) {
        int s = g_csr_src[p];
        float l = leakyf(AS[s] + adst);
        float mn = fmaxf(m, l);
        float sc = __expf(m - mn);
        float w = __expf(l - mn);
        const float *xr = XW + (size_t)s * DH;
        acc0 = acc0 * sc + w * xr[lane];
        acc1 = acc1 * sc + w * xr[lane + 32];
        acc2 = acc2 * sc + w * xr[lane + 64];
        ssum = ssum * sc + w;
        m = mn;
    }
    float inv = (end > start) ? 1.f / ssum : 0.f;
    float o0 = acc0 * inv + bias[lane];
    float o1 = acc1 * inv + bias[lane + 32];
    float o2 = acc2 * inv + bias[lane + 64];
    float *hg = H + (size_t)node * DH;
    hg[lane] = eluf(o0);
    hg[lane + 32] = eluf(o1);
    hg[lane + 64] = eluf(o2);
}

// ---------------- GRU gates + relu (updates X in place) ----------------------
__device__ __forceinline__ float gru1(float ir, float iz, float inn, float hr,
                                      float hz, float hn, float h) {
    float r = sigmf(ir + hr);
    float z = sigmf(iz + hz);
    float n = tanhf(inn + r * hn);
    float v = (1.f - z) * n + z * h;
    return fmaxf(v, 0.f);
}

__global__ __launch_bounds__(256) void gru_gate_kernel(const float *__restrict__ GI,
                                                       const float *__restrict__ GH,
                                                       float *__restrict__ X) {
    int idx = blockIdx.x * 256 + threadIdx.x;
    if (idx >= NN * 24) return;
    int node = idx / 24;
    int c = (idx - node * 24) * 4;
    const float *gi = GI + (size_t)node * 288;
    const float *gh = GH + (size_t)node * 288;
    float4 ir = *(const float4 *)(gi + c);
    float4 iz = *(const float4 *)(gi + 96 + c);
    float4 in_ = *(const float4 *)(gi + 192 + c);
    float4 hr = *(const float4 *)(gh + c);
    float4 hz = *(const float4 *)(gh + 96 + c);
    float4 hn = *(const float4 *)(gh + 192 + c);
    float *xp = X + (size_t)node * DH + c;
    float4 xo = *(const float4 *)xp;
    float4 res;
    res.x = gru1(ir.x, iz.x, in_.x, hr.x, hz.x, hn.x, xo.x);
    res.y = gru1(ir.y, iz.y, in_.y, hr.y, hz.y, hn.y, xo.y);
    res.z = gru1(ir.z, iz.z, in_.z, hr.z, hz.z, hn.z, xo.z);
    res.w = gru1(ir.w, iz.w, in_.w, hr.w, hz.w, hn.w, xo.w);
    *(float4 *)xp = res;
}

// ---------------- final layernorm (no affine) --------------------------------
__global__ __launch_bounds__(256) void ln_kernel(const float *__restrict__ X,
                                                 float *__restrict__ out) {
    int lane = threadIdx.x & 31;
    int node = blockIdx.x * 8 + (threadIdx.x >> 5);
    if (node >= NN) return;
    const float *xr = X + (size_t)node * DH;
    float a0 = xr[lane], a1 = xr[lane + 32], a2 = xr[lane + 64];
    float s = a0 + a1 + a2;
#pragma unroll
    for (int off = 16; off > 0; off >>= 1) s += __shfl_xor_sync(0xffffffffu, s, off);
    float mu = s * (1.f / 96.f);
    float d0 = a0 - mu, d1 = a1 - mu, d2 = a2 - mu;
    float ss = d0 * d0 + d1 * d1 + d2 * d2;
#pragma unroll
    for (int off = 16; off > 0; off >>= 1) ss += __shfl_xor_sync(0xffffffffu, ss, off);
    float inv = rsqrtf(ss * (1.f / 96.f) + 1e-5f);
    float *og = out + (size_t)node * DH;
    og[lane] = d0 * inv;
    og[lane + 32] = d1 * inv;
    og[lane + 64] = d2 * inv;
}

// ---------------- launch -----------------------------------------------------
extern "C" void kernel_launch(void* const* d_in, const int* in_sizes, int n_in,
                              void* d_out, int out_size) {
    const float *x = (const float *)d_in[0];
    const void *eidx = (const void *)d_in[1];
    const float *edge_attr = (const float *)d_in[2];
    const float *W_enter = (const float *)d_in[3];
    const float *b_enter = (const float *)d_in[4];
    const float *e_lin1 = (const float *)d_in[5];
    const float *e_lin2 = (const float *)d_in[6];
    const float *e_att_l = (const float *)d_in[7];
    const float *e_att_r = (const float *)d_in[8];
    const float *e_bias = (const float *)d_in[9];
    const float *gat_W = (const float *)d_in[10];
    const float *gat_att_src = (const float *)d_in[11];
    const float *gat_att_dst = (const float *)d_in[12];
    const float *gat_bias = (const float *)d_in[13];
    const float *gru_Wih = (const float *)d_in[14];
    const float *gru_Whh = (const float *)d_in[15];
    const float *gru_bih = (const float *)d_in[16];
    const float *gru_bhh = (const float *)d_in[17];
    float *out = (float *)d_out;

    // opt-in smem for K=96 GEMMs (not a stream op; executes immediately)
    const int SM96 = (96 * 100 + 64 * 98) * 4;
    const int SM64 = (64 * 100 + 64 * 66) * 4;
    cudaFuncSetAttribute(mm_kernel<96, ACT_NONE, false>,
                         cudaFuncAttributeMaxDynamicSharedMemorySize, SM96);
    cudaFuncSetAttribute(mm_kernel<96, ACT_ELU, false>,
                         cudaFuncAttributeMaxDynamicSharedMemorySize, SM96);
    cudaFuncSetAttribute(mm_kernel<96, ACT_BIAS, true>,
                         cudaFuncAttributeMaxDynamicSharedMemorySize, SM96);

    float *pX, *pU, *pAGG, *pH, *pGI, *pGH, *pAD, *pAS;
    cudaGetSymbolAddress((void **)&pX, g_X);
    cudaGetSymbolAddress((void **)&pU, g_U);
    cudaGetSymbolAddress((void **)&pAGG, g_AGG);
    cudaGetSymbolAddress((void **)&pH, g_H);
    cudaGetSymbolAddress((void **)&pGI, g_GI);
    cudaGetSymbolAddress((void **)&pGH, g_GH);
    cudaGetSymbolAddress((void **)&pAD, g_AD);
    cudaGetSymbolAddress((void **)&pAS, g_AS);

    const int EB = (NE + 255) / 256;     // 3125
    const int NB = (NN + 255) / 256;     // 196
    const int WB = (NN + 7) / 8;         // 6250 (warp-per-node kernels)
    const int RB = (NN + 63) / 64;       // 782  (GEMM row blocks)

    // edge_index dtype detection + extraction, then CSR build
    k_detect<<<1, 32>>>(eidx);
    k_extract<<<EB, 256>>>(eidx);
    k_zero_deg<<<NB, 256>>>();
    k_hist<<<EB, 256>>>();
    k_bsum<<<49, 1024>>>();
    k_bscan<<<1, 32>>>();
    k_scan<<<49, 1024>>>();
    k_scatter<<<EB, 256>>>();

    // entry: X = leaky(x @ W_enter + b_enter)
    mm_kernel<64, ACT_LEAKY, false><<<dim3(RB, 1), 128, SM64>>>(x, W_enter, b_enter,
                                                                pX, NN, 96);

    // --- Edge2dConv layer 0 ---
    mm_kernel<96, ACT_NONE, false><<<dim3(RB, 1), 128, SM96>>>(pX, e_lin1, nullptr,
                                                               pU, NN, 96);
    dots_kernel<<<WB, 256>>>(pX, e_att_r, nullptr, pAD, nullptr);
    edge0_agg_kernel<<<WB, 256>>>(pU, edge_attr, e_lin1 + 96 * 96, e_att_l, pAD, pAGG);
    mm_kernel<96, ACT_ELU, false><<<dim3(RB, 1), 128, SM96>>>(pAGG, e_lin2, e_bias,
                                                              pH, NN, 96);
    mm_kernel<96, ACT_BIAS, true><<<dim3(RB, 3), 128, SM96>>>(pH, gru_Wih, gru_bih,
                                                              pGI, NN, 288);
    mm_kernel<96, ACT_BIAS, true><<<dim3(RB, 3), 128, SM96>>>(pX, gru_Whh, gru_bhh,
                                                              pGH, NN, 288);
    gru_gate_kernel<<<(NN * 24 + 255) / 256, 256>>>(pGI, pGH, pX);

    // --- GAT layers ---
    for (int l = 0; l < 2; l++) {
        mm_kernel<96, ACT_NONE, false><<<dim3(RB, 1), 128, SM96>>>(
            pX, gat_W + (size_t)l * 96 * 96, nullptr, pU, NN, 96);
        dots_kernel<<<WB, 256>>>(pU, gat_att_src + l * 96, gat_att_dst + l * 96,
                                 pAS, pAD);
        gat_agg_kernel<<<WB, 256>>>(pU, pAS, pAD, gat_bias + l * 96, pH);
        mm_kernel<96, ACT_BIAS, true><<<dim3(RB, 3), 128, SM96>>>(
            pH, gru_Wih + (size_t)(l + 1) * 288 * 96, gru_bih + (l + 1) * 288, pGI,
            NN, 288);
        mm_kernel<96, ACT_BIAS, true><<<dim3(RB, 3), 128, SM96>>>(
            pX, gru_Whh + (size_t)(l + 1) * 288 * 96, gru_bhh + (l + 1) * 288, pGH,
            NN, 288);
        gru_gate_kernel<<<(NN * 24 + 255) / 256, 256>>>(pGI, pGH, pX);
    }

    ln_kernel<<<WB, 256>>>(pX, out);
}

// round 6
// speedup vs baseline: 1.1223x; 1.1223x over previous
#include <cuda_runtime.h>
#include <cstdint>

#define NN 50000
#define NE 800000
#define DH 96
#define DE 16

typedef unsigned long long ull;
typedef long long ll;

// ---------------- scratch: __device__ globals (no allocs allowed) ------------
__device__ float g_X[NN * DH];
__device__ float g_U[NN * DH];
__device__ float g_AGG[NN * DH];
__device__ float g_H[NN * DH];
__device__ float g_GI[NN * 3 * DH];
__device__ float g_GH[NN * 3 * DH];
__device__ float g_AD[NN];
__device__ float g_AS[NN];
__device__ int g_src[NE];
__device__ int g_dst[NE];
__device__ int g_deg[NN];
__device__ int g_rowp[NN + 1];
__device__ int g_cur[NN];
__device__ int g_bsum[64];
__device__ int g_is64;
__device__ int g_csr_src[NE];
__device__ int g_csr_eid[NE];

// ---------------- helpers ----------------------------------------------------
__device__ __forceinline__ void ffma2(ull &acc, ull a, ull w) {
    asm("fma.rn.f32x2 %0, %1, %2, %0;" : "+l"(acc) : "l"(a), "l"(w));
}
__device__ __forceinline__ ull pack2(float a) {
    ull r;
    unsigned ai = __float_as_uint(a);
    asm("mov.b64 %0, {%1, %1};" : "=l"(r) : "r"(ai));
    return r;
}
__device__ __forceinline__ float leakyf(float v) { return v >= 0.f ? v : 0.01f * v; }
__device__ __forceinline__ float eluf(float v) { return v > 0.f ? v : expm1f(v); }
__device__ __forceinline__ float sigmf(float v) { return 1.f / (1.f + __expf(-v)); }

// ---------------- edge_index dtype detection + extraction --------------------
__global__ void k_detect(const void *__restrict__ ei) {
    if (threadIdx.x == 0 && blockIdx.x == 0) {
        const ll *e64 = (const ll *)ei;
        int ok = 1;
        for (int i = 0; i < 64; i++) {
            ll v = e64[i];
            if (v < 0 || v >= NN) { ok = 0; break; }
        }
        g_is64 = ok;
    }
}

__global__ void k_zero_deg() {
    int i = blockIdx.x * blockDim.x + threadIdx.x;
    if (i < NN) g_deg[i] = 0;
}

// extract src/dst as int32 AND histogram dst in the same pass
__global__ void k_extract_hist(const void *__restrict__ ei) {
    int i = blockIdx.x * blockDim.x + threadIdx.x;
    if (i >= NE) return;
    int s, d;
    if (g_is64) {
        const ll *e64 = (const ll *)ei;
        s = (int)e64[i];
        d = (int)e64[NE + i];
    } else {
        const int *e32 = (const int *)ei;
        s = e32[i];
        d = e32[NE + i];
    }
    g_src[i] = s;
    g_dst[i] = d;
    atomicAdd(&g_deg[d], 1);
}

// ---------------- CSR build --------------------------------------------------
__global__ void k_bsum() {
    __shared__ int sred[32];
    int tid = threadIdx.x;
    int i = blockIdx.x * 1024 + tid;
    int v = (i < NN) ? g_deg[i] : 0;
#pragma unroll
    for (int off = 16; off > 0; off >>= 1) v += __shfl_xor_sync(0xffffffffu, v, off);
    if ((tid & 31) == 0) sred[tid >> 5] = v;
    __syncthreads();
    if (tid < 32) {
        int t = sred[tid];
#pragma unroll
        for (int off = 16; off > 0; off >>= 1) t += __shfl_xor_sync(0xffffffffu, t, off);
        if (tid == 0) g_bsum[blockIdx.x] = t;
    }
}

__global__ void k_bscan() {
    if (threadIdx.x == 0 && blockIdx.x == 0) {
        int s = 0;
        for (int b = 0; b < 49; b++) {
            int t = g_bsum[b];
            g_bsum[b] = s;
            s += t;
        }
        g_rowp[0] = 0;
    }
}

__global__ void k_scan() {
    __shared__ int sb[1024];
    int tid = threadIdx.x;
    int i = blockIdx.x * 1024 + tid;
    int v = (i < NN) ? g_deg[i] : 0;
    sb[tid] = v;
    __syncthreads();
    for (int off = 1; off < 1024; off <<= 1) {
        int t = (tid >= off) ? sb[tid - off] : 0;
        __syncthreads();
        sb[tid] += t;
        __syncthreads();
    }
    if (i < NN) {
        int incl = sb[tid] + g_bsum[blockIdx.x];
        g_rowp[i + 1] = incl;
        g_cur[i] = incl - v;
    }
}

__global__ void k_scatter() {
    int i = blockIdx.x * blockDim.x + threadIdx.x;
    if (i < NE) {
        int d = g_dst[i];
        int p = atomicAdd(&g_cur[d], 1);
        g_csr_src[p] = g_src[i];
        g_csr_eid[p] = i;
    }
}

// ---------------- GEMM: C[nrows,Mfull] = act(A[nrows,K] @ W (+b)) ------------
// 128-row blocks, 256 threads, per-thread 4x12 tile, f32x2 packed FMA.
// Optional fused per-row dot products o1 = row.att1, o2 = row.att2 (DOTS).
#define ACT_NONE 0
#define ACT_BIAS 1
#define ACT_LEAKY 2
#define ACT_ELU 3

template <int K, int ACT, bool WT, bool DOTS>
__global__ __launch_bounds__(256) void mm_kernel(
    const float *__restrict__ A, const float *__restrict__ W,
    const float *__restrict__ bias, float *__restrict__ C,
    const float *__restrict__ att1, const float *__restrict__ att2,
    float *__restrict__ o1, float *__restrict__ o2, int nrows, int Mfull) {
    constexpr int SWS = 100;     // 96 + pad, 16B-aligned vector LDS
    constexpr int SAS = K + 2;   // row stride -> bank rotation across rg
    extern __shared__ float sm[];
    float *sW = sm;                       // [K][SWS]
    float *sA = sm + K * SWS;             // [128][SAS]
    float *sAt = sA + 128 * SAS;          // [192] (only if DOTS)
    const int tid = threadIdx.x;
    const int m0 = blockIdx.y * 96;
    const int r0 = blockIdx.x * 128;

    if (!WT) {
        for (int i = tid; i < K * 96; i += 256) {
            int k = i / 96, j = i - k * 96;
            sW[k * SWS + j] = W[(size_t)k * Mfull + m0 + j];
        }
    } else {
        for (int i = tid; i < 96 * K; i += 256) {
            int j = i / K, k = i - j * K;
            sW[k * SWS + j] = W[(size_t)(m0 + j) * K + k];
        }
    }
    for (int i = tid; i < 128 * K; i += 256) {
        int r = i / K, k = i - r * K;
        int row = r0 + r;
        sA[r * SAS + k] = (row < nrows) ? A[(size_t)row * K + k] : 0.f;
    }
    if (DOTS) {
        if (tid < 96) sAt[tid] = att1[tid];
        if (tid >= 128 && tid < 224) sAt[tid - 32] = att2 ? att2[tid - 128] : 0.f;
    }
    __syncthreads();

    const int ct = tid & 7;    // 8 col-threads * 12 cols = 96
    const int rg = tid >> 3;   // 32 row-groups * 4 rows = 128
    const float *wp = sW + 12 * ct;
    const float *ap = sA + (rg * 4) * SAS;

    ull acc[4][6];
#pragma unroll
    for (int r = 0; r < 4; r++)
#pragma unroll
        for (int q = 0; q < 6; q++) acc[r][q] = 0ull;

#pragma unroll 2
    for (int k = 0; k < K; k++) {
        ulonglong2 wA = *(const ulonglong2 *)(wp + (size_t)k * SWS);
        ulonglong2 wB = *(const ulonglong2 *)(wp + (size_t)k * SWS + 4);
        ulonglong2 wC = *(const ulonglong2 *)(wp + (size_t)k * SWS + 8);
        ull w0 = wA.x, w1 = wA.y, w2 = wB.x, w3 = wB.y, w4 = wC.x, w5 = wC.y;
#pragma unroll
        for (int r = 0; r < 4; r++) {
            ull a2 = pack2(ap[r * SAS + k]);
            ffma2(acc[r][0], a2, w0);
            ffma2(acc[r][1], a2, w1);
            ffma2(acc[r][2], a2, w2);
            ffma2(acc[r][3], a2, w3);
            ffma2(acc[r][4], a2, w4);
            ffma2(acc[r][5], a2, w5);
        }
    }

#pragma unroll
    for (int r = 0; r < 4; r++) {
        int row = r0 + rg * 4 + r;
        if (row >= nrows) break;
        float *cp = C + (size_t)row * Mfull + m0 + 12 * ct;
        float p1 = 0.f, p2 = 0.f;
#pragma unroll
        for (int q = 0; q < 6; q++) {
            float lo = __uint_as_float((unsigned)acc[r][q]);
            float hi = __uint_as_float((unsigned)(acc[r][q] >> 32));
            if (ACT != ACT_NONE) {
                float2 bb = *(const float2 *)(bias + m0 + 12 * ct + 2 * q);
                lo += bb.x;
                hi += bb.y;
                if (ACT == ACT_LEAKY) {
                    lo = leakyf(lo);
                    hi = leakyf(hi);
                } else if (ACT == ACT_ELU) {
                    lo = eluf(lo);
                    hi = eluf(hi);
                }
            }
            *(float2 *)(cp + 2 * q) = make_float2(lo, hi);
            if (DOTS) {
                int c = 12 * ct + 2 * q;
                p1 = fmaf(lo, sAt[c], fmaf(hi, sAt[c + 1], p1));
                p2 = fmaf(lo, sAt[96 + c], fmaf(hi, sAt[96 + c + 1], p2));
            }
        }
        if (DOTS) {
            // row owned by 8 consecutive lanes (ct = lane&7)
#pragma unroll
            for (int off = 4; off > 0; off >>= 1) {
                p1 += __shfl_xor_sync(0xffffffffu, p1, off);
                p2 += __shfl_xor_sync(0xffffffffu, p2, off);
            }
            if (ct == 0) {
                o1[row] = p1;
                if (o2) o2[row] = p2;
            }
        }
    }
}

// ---------------- Edge2dConv aggregation (warp per dst, online softmax) ------
// We (16x96) held in registers per lane: 3 columns x 16 k. Zero LDS per edge.
__global__ __launch_bounds__(128) void edge0_agg_kernel(
    const float *__restrict__ U, const float *__restrict__ edge_attr,
    const float *__restrict__ We, const float *__restrict__ att_l,
    const float *__restrict__ AD, float *__restrict__ AGG) {
    __shared__ float sWe[DE * DH];
    __shared__ float sAtt[DH];
    int tid = threadIdx.x;
    for (int i = tid; i < DE * DH; i += 128) sWe[i] = We[i];
    if (tid < DH) sAtt[tid] = att_l[tid];
    __syncthreads();

    int lane = tid & 31;
    float we0[DE], we1[DE], we2[DE];
#pragma unroll
    for (int k = 0; k < DE; k++) {
        we0[k] = sWe[k * DH + lane];
        we1[k] = sWe[k * DH + lane + 32];
        we2[k] = sWe[k * DH + lane + 64];
    }
    float at0 = sAtt[lane], at1 = sAtt[lane + 32], at2 = sAtt[lane + 64];

    int node = blockIdx.x * 4 + (tid >> 5);
    if (node >= NN) return;
    int start = g_rowp[node], end = g_rowp[node + 1];
    float adst = AD[node];
    float acc0 = 0.f, acc1 = 0.f, acc2 = 0.f, ssum = 0.f, m = -1e30f;

    for (int p = start; p < end; p++) {
        int s = g_csr_src[p];
        int eid = g_csr_eid[p];
        const float4 *ea4 = (const float4 *)(edge_attr + (size_t)eid * DE);
        float4 E0 = ea4[0], E1 = ea4[1], E2 = ea4[2], E3 = ea4[3];
        float ea[16] = {E0.x, E0.y, E0.z, E0.w, E1.x, E1.y, E1.z, E1.w,
                        E2.x, E2.y, E2.z, E2.w, E3.x, E3.y, E3.z, E3.w};
        float v0 = 0.f, v1 = 0.f, v2 = 0.f;
#pragma unroll
        for (int k = 0; k < DE; k++) {
            v0 = fmaf(ea[k], we0[k], v0);
            v1 = fmaf(ea[k], we1[k], v1);
            v2 = fmaf(ea[k], we2[k], v2);
        }
        const float *ur = U + (size_t)s * DH;
        float mj0 = leakyf(ur[lane] + v0);
        float mj1 = leakyf(ur[lane + 32] + v1);
        float mj2 = leakyf(ur[lane + 64] + v2);
        float part = mj0 * at0 + mj1 * at1 + mj2 * at2;
#pragma unroll
        for (int off = 16; off > 0; off >>= 1)
            part += __shfl_xor_sync(0xffffffffu, part, off);
        float l = leakyf(part + adst);
        float mn = fmaxf(m, l);
        float sc = __expf(m - mn);
        float w = __expf(l - mn);
        acc0 = acc0 * sc + w * mj0;
        acc1 = acc1 * sc + w * mj1;
        acc2 = acc2 * sc + w * mj2;
        ssum = ssum * sc + w;
        m = mn;
    }
    float inv = (end > start) ? 1.f / ssum : 0.f;
    float *og = AGG + (size_t)node * DH;
    og[lane] = acc0 * inv;
    og[lane + 32] = acc1 * inv;
    og[lane + 64] = acc2 * inv;
}

// ---------------- GAT aggregation (warp per dst) + fused bias/elu ------------
__global__ __launch_bounds__(256) void gat_agg_kernel(const float *__restrict__ XW,
                                                      const float *__restrict__ AS,
                                                      const float *__restrict__ AD,
                                                      const float *__restrict__ bias,
                                                      float *__restrict__ H) {
    int lane = threadIdx.x & 31;
    int node = blockIdx.x * 8 + (threadIdx.x >> 5);
    if (node >= NN) return;
    int start = g_rowp[node], end = g_rowp[node + 1];
    float adst = AD[node];
    float acc0 = 0.f, acc1 = 0.f, acc2 = 0.f, ssum = 0.f, m = -1e30f;
    for (int p = start; p < end; p++) {
        int s = g_csr_src[p];
        float l = leakyf(AS[s] + adst);
        float mn = fmaxf(m, l);
        float sc = __expf(m - mn);
        float w = __expf(l - mn);
        const float *xr = XW + (size_t)s * DH;
        acc0 = acc0 * sc + w * xr[lane];
        acc1 = acc1 * sc + w * xr[lane + 32];
        acc2 = acc2 * sc + w * xr[lane + 64];
        ssum = ssum * sc + w;
        m = mn;
    }
    float inv = (end > start) ? 1.f / ssum : 0.f;
    float o0 = acc0 * inv + bias[lane];
    float o1 = acc1 * inv + bias[lane + 32];
    float o2 = acc2 * inv + bias[lane + 64];
    float *hg = H + (size_t)node * DH;
    hg[lane] = eluf(o0);
    hg[lane + 32] = eluf(o1);
    hg[lane + 64] = eluf(o2);
}

// ---------------- GRU gates + relu (updates X in place) ----------------------
__device__ __forceinline__ float gru1(float ir, float iz, float inn, float hr,
                                      float hz, float hn, float h) {
    float r = sigmf(ir + hr);
    float z = sigmf(iz + hz);
    float n = tanhf(inn + r * hn);
    float v = (1.f - z) * n + z * h;
    return fmaxf(v, 0.f);
}

__global__ __launch_bounds__(256) void gru_gate_kernel(const float *__restrict__ GI,
                                                       const float *__restrict__ GH,
                                                       float *__restrict__ X) {
    int idx = blockIdx.x * 256 + threadIdx.x;
    if (idx >= NN * 24) return;
    int node = idx / 24;
    int c = (idx - node * 24) * 4;
    const float *gi = GI + (size_t)node * 288;
    const float *gh = GH + (size_t)node * 288;
    float4 ir = *(const float4 *)(gi + c);
    float4 iz = *(const float4 *)(gi + 96 + c);
    float4 in_ = *(const float4 *)(gi + 192 + c);
    float4 hr = *(const float4 *)(gh + c);
    float4 hz = *(const float4 *)(gh + 96 + c);
    float4 hn = *(const float4 *)(gh + 192 + c);
    float *xp = X + (size_t)node * DH + c;
    float4 xo = *(const float4 *)xp;
    float4 res;
    res.x = gru1(ir.x, iz.x, in_.x, hr.x, hz.x, hn.x, xo.x);
    res.y = gru1(ir.y, iz.y, in_.y, hr.y, hz.y, hn.y, xo.y);
    res.z = gru1(ir.z, iz.z, in_.z, hr.z, hz.z, hn.z, xo.z);
    res.w = gru1(ir.w, iz.w, in_.w, hr.w, hz.w, hn.w, xo.w);
    *(float4 *)xp = res;
}

// ---------------- final layernorm (no affine) --------------------------------
__global__ __launch_bounds__(256) void ln_kernel(const float *__restrict__ X,
                                                 float *__restrict__ out) {
    int lane = threadIdx.x & 31;
    int node = blockIdx.x * 8 + (threadIdx.x >> 5);
    if (node >= NN) return;
    const float *xr = X + (size_t)node * DH;
    float a0 = xr[lane], a1 = xr[lane + 32], a2 = xr[lane + 64];
    float s = a0 + a1 + a2;
#pragma unroll
    for (int off = 16; off > 0; off >>= 1) s += __shfl_xor_sync(0xffffffffu, s, off);
    float mu = s * (1.f / 96.f);
    float d0 = a0 - mu, d1 = a1 - mu, d2 = a2 - mu;
    float ss = d0 * d0 + d1 * d1 + d2 * d2;
#pragma unroll
    for (int off = 16; off > 0; off >>= 1) ss += __shfl_xor_sync(0xffffffffu, ss, off);
    float inv = rsqrtf(ss * (1.f / 96.f) + 1e-5f);
    float *og = out + (size_t)node * DH;
    og[lane] = d0 * inv;
    og[lane + 32] = d1 * inv;
    og[lane + 64] = d2 * inv;
}

// ---------------- launch -----------------------------------------------------
extern "C" void kernel_launch(void* const* d_in, const int* in_sizes, int n_in,
                              void* d_out, int out_size) {
    const float *x = (const float *)d_in[0];
    const void *eidx = (const void *)d_in[1];
    const float *edge_attr = (const float *)d_in[2];
    const float *W_enter = (const float *)d_in[3];
    const float *b_enter = (const float *)d_in[4];
    const float *e_lin1 = (const float *)d_in[5];
    const float *e_lin2 = (const float *)d_in[6];
    const float *e_att_l = (const float *)d_in[7];
    const float *e_att_r = (const float *)d_in[8];
    const float *e_bias = (const float *)d_in[9];
    const float *gat_W = (const float *)d_in[10];
    const float *gat_att_src = (const float *)d_in[11];
    const float *gat_att_dst = (const float *)d_in[12];
    const float *gat_bias = (const float *)d_in[13];
    const float *gru_Wih = (const float *)d_in[14];
    const float *gru_Whh = (const float *)d_in[15];
    const float *gru_bih = (const float *)d_in[16];
    const float *gru_bhh = (const float *)d_in[17];
    float *out = (float *)d_out;

    const int SM96 = (96 * 100 + 128 * 98 + 192) * 4;   // 89344 B
    const int SM64 = (64 * 100 + 128 * 66 + 192) * 4;   // 60160 B
    cudaFuncSetAttribute(mm_kernel<64, ACT_LEAKY, false, true>,
                         cudaFuncAttributeMaxDynamicSharedMemorySize, SM64);
    cudaFuncSetAttribute(mm_kernel<96, ACT_NONE, false, false>,
                         cudaFuncAttributeMaxDynamicSharedMemorySize, SM96);
    cudaFuncSetAttribute(mm_kernel<96, ACT_NONE, false, true>,
                         cudaFuncAttributeMaxDynamicSharedMemorySize, SM96);
    cudaFuncSetAttribute(mm_kernel<96, ACT_ELU, false, false>,
                         cudaFuncAttributeMaxDynamicSharedMemorySize, SM96);
    cudaFuncSetAttribute(mm_kernel<96, ACT_BIAS, true, false>,
                         cudaFuncAttributeMaxDynamicSharedMemorySize, SM96);

    float *pX, *pU, *pAGG, *pH, *pGI, *pGH, *pAD, *pAS;
    cudaGetSymbolAddress((void **)&pX, g_X);
    cudaGetSymbolAddress((void **)&pU, g_U);
    cudaGetSymbolAddress((void **)&pAGG, g_AGG);
    cudaGetSymbolAddress((void **)&pH, g_H);
    cudaGetSymbolAddress((void **)&pGI, g_GI);
    cudaGetSymbolAddress((void **)&pGH, g_GH);
    cudaGetSymbolAddress((void **)&pAD, g_AD);
    cudaGetSymbolAddress((void **)&pAS, g_AS);

    const int EB = (NE + 255) / 256;     // 3125
    const int NB = (NN + 255) / 256;     // 196
    const int WB8 = (NN + 7) / 8;        // warp-per-node kernels, 256 thr
    const int WB4 = (NN + 3) / 4;        // edge0 agg, 128 thr
    const int RB = (NN + 127) / 128;     // 391 GEMM row blocks

    // entry first: X = leaky(x @ W_enter + b_enter), fused AD0 = X @ e_att_r
    mm_kernel<64, ACT_LEAKY, false, true><<<dim3(RB, 1), 256, SM64>>>(
        x, W_enter, b_enter, pX, e_att_r, nullptr, pAD, nullptr, NN, 96);

    // CSR build (independent of entry GEMM)
    k_detect<<<1, 32>>>(eidx);
    k_zero_deg<<<NB, 256>>>();
    k_extract_hist<<<EB, 256>>>(eidx);
    k_bsum<<<49, 1024>>>();
    k_bscan<<<1, 32>>>();
    k_scan<<<49, 1024>>>();
    k_scatter<<<EB, 256>>>();

    // --- Edge2dConv layer 0 ---
    mm_kernel<96, ACT_NONE, false, false><<<dim3(RB, 1), 256, SM96>>>(
        pX, e_lin1, nullptr, pU, nullptr, nullptr, nullptr, nullptr, NN, 96);
    edge0_agg_kernel<<<WB4, 128>>>(pU, edge_attr, e_lin1 + 96 * 96, e_att_l, pAD,
                                   pAGG);
    mm_kernel<96, ACT_ELU, false, false><<<dim3(RB, 1), 256, SM96>>>(
        pAGG, e_lin2, e_bias, pH, nullptr, nullptr, nullptr, nullptr, NN, 96);
    mm_kernel<96, ACT_BIAS, true, false><<<dim3(RB, 3), 256, SM96>>>(
        pH, gru_Wih, gru_bih, pGI, nullptr, nullptr, nullptr, nullptr, NN, 288);
    mm_kernel<96, ACT_BIAS, true, false><<<dim3(RB, 3), 256, SM96>>>(
        pX, gru_Whh, gru_bhh, pGH, nullptr, nullptr, nullptr, nullptr, NN, 288);
    gru_gate_kernel<<<(NN * 24 + 255) / 256, 256>>>(pGI, pGH, pX);

    // --- GAT layers ---
    for (int l = 0; l < 2; l++) {
        mm_kernel<96, ACT_NONE, false, true><<<dim3(RB, 1), 256, SM96>>>(
            pX, gat_W + (size_t)l * 96 * 96, nullptr, pU, gat_att_src + l * 96,
            gat_att_dst + l * 96, pAS, pAD, NN, 96);
        gat_agg_kernel<<<WB8, 256>>>(pU, pAS, pAD, gat_bias + l * 96, pH);
        mm_kernel<96, ACT_BIAS, true, false><<<dim3(RB, 3), 256, SM96>>>(
            pH, gru_Wih + (size_t)(l + 1) * 288 * 96, gru_bih + (l + 1) * 288, pGI,
            nullptr, nullptr, nullptr, nullptr, NN, 288);
        mm_kernel<96, ACT_BIAS, true, false><<<dim3(RB, 3), 256, SM96>>>(
            pX, gru_Whh + (size_t)(l + 1) * 288 * 96, gru_bhh + (l + 1) * 288, pGH,
            nullptr, nullptr, nullptr, nullptr, NN, 288);
        gru_gate_kernel<<<(NN * 24 + 255) / 256, 256>>>(pGI, pGH, pX);
    }

    ln_kernel<<<WB8, 256>>>(pX, out);
}

// round 8
// speedup vs baseline: 1.2360x; 1.1013x over previous
#include <cuda_runtime.h>
#include <cstdint>

#define NN 50000
#define NE 800000
#define DH 96
#define DE 16

typedef unsigned long long ull;
typedef long long ll;

// ---------------- scratch: __device__ globals (no allocs allowed) ------------
__device__ float g_X[NN * DH];
__device__ float g_U[NN * DH];
__device__ float g_AGG[NN * DH];
__device__ float g_H[NN * DH];
__device__ float g_GI[NN * 3 * DH];
__device__ float g_GH[NN * 3 * DH];
__device__ float g_AD[NN];
__device__ float g_AS[NN];
__device__ int g_src[NE];
__device__ int g_dst[NE];
__device__ int g_deg[NN];
__device__ int g_rowp[NN + 1];
__device__ int g_cur[NN];
__device__ int g_bsum[64];
__device__ int g_is64;
__device__ int g_csr_src[NE];
__device__ int g_csr_eid[NE];

// ---------------- helpers ----------------------------------------------------
__device__ __forceinline__ void ffma2(ull &acc, ull a, ull w) {
    asm("fma.rn.f32x2 %0, %1, %2, %0;" : "+l"(acc) : "l"(a), "l"(w));
}
__device__ __forceinline__ ull pack2(float a) {
    ull r;
    unsigned ai = __float_as_uint(a);
    asm("mov.b64 %0, {%1, %1};" : "=l"(r) : "r"(ai));
    return r;
}
__device__ __forceinline__ float leakyf(float v) { return v >= 0.f ? v : 0.01f * v; }
__device__ __forceinline__ float eluf(float v) { return v > 0.f ? v : expm1f(v); }
__device__ __forceinline__ float sigmf(float v) { return 1.f / (1.f + __expf(-v)); }
__device__ __forceinline__ float tanhfast(float x) {
    float y;
    asm("tanh.approx.f32 %0, %1;" : "=f"(y) : "f"(x));
    return y;
}

// ---------------- zero deg + edge_index dtype detection ----------------------
__global__ void k_zero_detect(const void *__restrict__ ei) {
    int i = blockIdx.x * blockDim.x + threadIdx.x;
    if (i < NN) g_deg[i] = 0;
    if (i == 0) {
        const ll *e64 = (const ll *)ei;
        int ok = 1;
        for (int j = 0; j < 64; j++) {
            ll v = e64[j];
            if (v < 0 || v >= NN) { ok = 0; break; }
        }
        g_is64 = ok;
    }
}

// extract src/dst as int32 AND histogram dst in the same pass
__global__ void k_extract_hist(const void *__restrict__ ei) {
    int i = blockIdx.x * blockDim.x + threadIdx.x;
    if (i >= NE) return;
    int s, d;
    if (g_is64) {
        const ll *e64 = (const ll *)ei;
        s = (int)e64[i];
        d = (int)e64[NE + i];
    } else {
        const int *e32 = (const int *)ei;
        s = e32[i];
        d = e32[NE + i];
    }
    g_src[i] = s;
    g_dst[i] = d;
    atomicAdd(&g_deg[d], 1);
}

// ---------------- CSR build --------------------------------------------------
__global__ void k_bsum() {
    __shared__ int sred[32];
    int tid = threadIdx.x;
    int i = blockIdx.x * 1024 + tid;
    int v = (i < NN) ? g_deg[i] : 0;
#pragma unroll
    for (int off = 16; off > 0; off >>= 1) v += __shfl_xor_sync(0xffffffffu, v, off);
    if ((tid & 31) == 0) sred[tid >> 5] = v;
    __syncthreads();
    if (tid < 32) {
        int t = sred[tid];
#pragma unroll
        for (int off = 16; off > 0; off >>= 1) t += __shfl_xor_sync(0xffffffffu, t, off);
        if (tid == 0) g_bsum[blockIdx.x] = t;
    }
}

__global__ void k_bscan() {
    if (threadIdx.x == 0 && blockIdx.x == 0) {
        int s = 0;
        for (int b = 0; b < 49; b++) {
            int t = g_bsum[b];
            g_bsum[b] = s;
            s += t;
        }
        g_rowp[0] = 0;
    }
}

__global__ void k_scan() {
    __shared__ int sb[1024];
    int tid = threadIdx.x;
    int i = blockIdx.x * 1024 + tid;
    int v = (i < NN) ? g_deg[i] : 0;
    sb[tid] = v;
    __syncthreads();
    for (int off = 1; off < 1024; off <<= 1) {
        int t = (tid >= off) ? sb[tid - off] : 0;
        __syncthreads();
        sb[tid] += t;
        __syncthreads();
    }
    if (i < NN) {
        int incl = sb[tid] + g_bsum[blockIdx.x];
        g_rowp[i + 1] = incl;
        g_cur[i] = incl - v;
    }
}

__global__ void k_scatter() {
    int i = blockIdx.x * blockDim.x + threadIdx.x;
    if (i < NE) {
        int d = g_dst[i];
        int p = atomicAdd(&g_cur[d], 1);
        g_csr_src[p] = g_src[i];
        g_csr_eid[p] = i;
    }
}

// ---------------- GEMM: C[nrows,Mfull] = act(A[nrows,K] @ W (+b)) ------------
// 128-row blocks, 256 threads, per-thread 4x12 tile, f32x2 packed FMA.
// Optional fused per-row dot products o1 = row.att1, o2 = row.att2 (DOTS).
#define ACT_NONE 0
#define ACT_BIAS 1
#define ACT_LEAKY 2
#define ACT_ELU 3

template <int K, int ACT, bool WT, bool DOTS>
__global__ __launch_bounds__(256) void mm_kernel(
    const float *__restrict__ A, const float *__restrict__ W,
    const float *__restrict__ bias, float *__restrict__ C,
    const float *__restrict__ att1, const float *__restrict__ att2,
    float *__restrict__ o1, float *__restrict__ o2, int nrows, int Mfull) {
    constexpr int SWS = 100;     // 96 + pad, 16B-aligned vector LDS
    constexpr int SAS = K + 2;   // row stride -> bank rotation across rg
    constexpr int KC = K / 4;
    extern __shared__ float sm[];
    float *sW = sm;                       // [K][SWS]
    float *sA = sm + K * SWS;             // [128][SAS]
    float *sAt = sA + 128 * SAS;          // [192] (only if DOTS)
    const int tid = threadIdx.x;
    const int m0 = blockIdx.y * 96;
    const int r0 = blockIdx.x * 128;

    if (!WT) {
        // W [K, Mfull] row-major: float4 along columns
        for (int i = tid; i < K * 24; i += 256) {
            int k = i / 24, j4 = (i - k * 24) * 4;
            float4 v = *(const float4 *)(W + (size_t)k * Mfull + m0 + j4);
            float *d = &sW[k * SWS + j4];
            d[0] = v.x; d[1] = v.y; d[2] = v.z; d[3] = v.w;
        }
    } else {
        // W [Mfull, K] row-major: float4 along k, transposed store
        for (int i = tid; i < 96 * KC; i += 256) {
            int j = i / KC, k4 = (i - j * KC) * 4;
            float4 v = *(const float4 *)(W + (size_t)(m0 + j) * K + k4);
            sW[(k4 + 0) * SWS + j] = v.x;
            sW[(k4 + 1) * SWS + j] = v.y;
            sW[(k4 + 2) * SWS + j] = v.z;
            sW[(k4 + 3) * SWS + j] = v.w;
        }
    }
    for (int i = tid; i < 128 * KC; i += 256) {
        int r = i / KC, k4 = (i - r * KC) * 4;
        int row = r0 + r;
        float4 v = (row < nrows) ? *(const float4 *)(A + (size_t)row * K + k4)
                                 : make_float4(0.f, 0.f, 0.f, 0.f);
        float *d = &sA[r * SAS + k4];
        d[0] = v.x; d[1] = v.y; d[2] = v.z; d[3] = v.w;
    }
    if (DOTS) {
        if (tid < 96) sAt[tid] = att1[tid];
        if (tid >= 128 && tid < 224) sAt[tid - 32] = att2 ? att2[tid - 128] : 0.f;
    }
    __syncthreads();

    const int ct = tid & 7;    // 8 col-threads * 12 cols = 96
    const int rg = tid >> 3;   // 32 row-groups * 4 rows = 128
    const float *wp = sW + 12 * ct;
    const float *ap = sA + (rg * 4) * SAS;

    ull acc[4][6];
#pragma unroll
    for (int r = 0; r < 4; r++)
#pragma unroll
        for (int q = 0; q < 6; q++) acc[r][q] = 0ull;

#pragma unroll 2
    for (int k = 0; k < K; k++) {
        ulonglong2 wA = *(const ulonglong2 *)(wp + (size_t)k * SWS);
        ulonglong2 wB = *(const ulonglong2 *)(wp + (size_t)k * SWS + 4);
        ulonglong2 wC = *(const ulonglong2 *)(wp + (size_t)k * SWS + 8);
        ull w0 = wA.x, w1 = wA.y, w2 = wB.x, w3 = wB.y, w4 = wC.x, w5 = wC.y;
#pragma unroll
        for (int r = 0; r < 4; r++) {
            ull a2 = pack2(ap[r * SAS + k]);
            ffma2(acc[r][0], a2, w0);
            ffma2(acc[r][1], a2, w1);
            ffma2(acc[r][2], a2, w2);
            ffma2(acc[r][3], a2, w3);
            ffma2(acc[r][4], a2, w4);
            ffma2(acc[r][5], a2, w5);
        }
    }

#pragma unroll
    for (int r = 0; r < 4; r++) {
        int row = r0 + rg * 4 + r;
        if (row >= nrows) break;
        float *cp = C + (size_t)row * Mfull + m0 + 12 * ct;
        float p1 = 0.f, p2 = 0.f;
#pragma unroll
        for (int q = 0; q < 6; q++) {
            float lo = __uint_as_float((unsigned)acc[r][q]);
            float hi = __uint_as_float((unsigned)(acc[r][q] >> 32));
            if (ACT != ACT_NONE) {
                float2 bb = *(const float2 *)(bias + m0 + 12 * ct + 2 * q);
                lo += bb.x;
                hi += bb.y;
                if (ACT == ACT_LEAKY) {
                    lo = leakyf(lo);
                    hi = leakyf(hi);
                } else if (ACT == ACT_ELU) {
                    lo = eluf(lo);
                    hi = eluf(hi);
                }
            }
            *(float2 *)(cp + 2 * q) = make_float2(lo, hi);
            if (DOTS) {
                int c = 12 * ct + 2 * q;
                p1 = fmaf(lo, sAt[c], fmaf(hi, sAt[c + 1], p1));
                p2 = fmaf(lo, sAt[96 + c], fmaf(hi, sAt[96 + c + 1], p2));
            }
        }
        if (DOTS) {
            // row owned by 8 consecutive lanes (ct = lane&7)
#pragma unroll
            for (int off = 4; off > 0; off >>= 1) {
                p1 += __shfl_xor_sync(0xffffffffu, p1, off);
                p2 += __shfl_xor_sync(0xffffffffu, p2, off);
            }
            if (ct == 0) {
                o1[row] = p1;
                if (o2) o2[row] = p2;
            }
        }
    }
}

// ---------------- Edge2dConv aggregation (warp per dst, online softmax) ------
// We (16x96) in registers per lane. Next-edge data prefetched (MLP=2).
__global__ __launch_bounds__(128) void edge0_agg_kernel(
    const float *__restrict__ U, const float *__restrict__ edge_attr,
    const float *__restrict__ We, const float *__restrict__ att_l,
    const float *__restrict__ AD, float *__restrict__ AGG) {
    __shared__ float sWe[DE * DH];
    __shared__ float sAtt[DH];
    int tid = threadIdx.x;
    for (int i = tid; i < DE * DH; i += 128) sWe[i] = We[i];
    if (tid < DH) sAtt[tid] = att_l[tid];
    __syncthreads();

    int lane = tid & 31;
    float we0[DE], we1[DE], we2[DE];
#pragma unroll
    for (int k = 0; k < DE; k++) {
        we0[k] = sWe[k * DH + lane];
        we1[k] = sWe[k * DH + lane + 32];
        we2[k] = sWe[k * DH + lane + 64];
    }
    float at0 = sAtt[lane], at1 = sAtt[lane + 32], at2 = sAtt[lane + 64];

    int node = blockIdx.x * 4 + (tid >> 5);
    if (node >= NN) return;
    int start = g_rowp[node], end = g_rowp[node + 1];
    float adst = AD[node];
    float acc0 = 0.f, acc1 = 0.f, acc2 = 0.f, ssum = 0.f, m = -1e30f;

    // prefetch slot (current)
    float4 c0, c1, c2, c3;
    float cu0, cu1, cu2;
    if (start < end) {
        int s = g_csr_src[start];
        int eid = g_csr_eid[start];
        const float4 *ea4 = (const float4 *)(edge_attr + (size_t)eid * DE);
        c0 = ea4[0]; c1 = ea4[1]; c2 = ea4[2]; c3 = ea4[3];
        const float *ur = U + (size_t)s * DH;
        cu0 = ur[lane]; cu1 = ur[lane + 32]; cu2 = ur[lane + 64];
    }

    for (int p = start; p < end; p++) {
        // prefetch next
        float4 n0, n1, n2, n3;
        float nu0 = 0.f, nu1 = 0.f, nu2 = 0.f;
        n0 = n1 = n2 = n3 = make_float4(0.f, 0.f, 0.f, 0.f);
        if (p + 1 < end) {
            int sn = g_csr_src[p + 1];
            int en = g_csr_eid[p + 1];
            const float4 *ea4 = (const float4 *)(edge_attr + (size_t)en * DE);
            n0 = ea4[0]; n1 = ea4[1]; n2 = ea4[2]; n3 = ea4[3];
            const float *ur = U + (size_t)sn * DH;
            nu0 = ur[lane]; nu1 = ur[lane + 32]; nu2 = ur[lane + 64];
        }
        // compute current
        float ea[16] = {c0.x, c0.y, c0.z, c0.w, c1.x, c1.y, c1.z, c1.w,
                        c2.x, c2.y, c2.z, c2.w, c3.x, c3.y, c3.z, c3.w};
        float v0 = 0.f, v1 = 0.f, v2 = 0.f;
#pragma unroll
        for (int k = 0; k < DE; k++) {
            v0 = fmaf(ea[k], we0[k], v0);
            v1 = fmaf(ea[k], we1[k], v1);
            v2 = fmaf(ea[k], we2[k], v2);
        }
        float mj0 = leakyf(cu0 + v0);
        float mj1 = leakyf(cu1 + v1);
        float mj2 = leakyf(cu2 + v2);
        float part = mj0 * at0 + mj1 * at1 + mj2 * at2;
#pragma unroll
        for (int off = 16; off > 0; off >>= 1)
            part += __shfl_xor_sync(0xffffffffu, part, off);
        float l = leakyf(part + adst);
        float mn = fmaxf(m, l);
        float sc = __expf(m - mn);
        float w = __expf(l - mn);
        acc0 = acc0 * sc + w * mj0;
        acc1 = acc1 * sc + w * mj1;
        acc2 = acc2 * sc + w * mj2;
        ssum = ssum * sc + w;
        m = mn;
        // rotate
        c0 = n0; c1 = n1; c2 = n2; c3 = n3;
        cu0 = nu0; cu1 = nu1; cu2 = nu2;
    }
    float inv = (end > start) ? 1.f / ssum : 0.f;
    float *og = AGG + (size_t)node * DH;
    og[lane] = acc0 * inv;
    og[lane + 32] = acc1 * inv;
    og[lane + 64] = acc2 * inv;
}

// ---------------- GAT aggregation (warp per dst) + fused bias/elu ------------
__global__ __launch_bounds__(256) void gat_agg_kernel(const float *__restrict__ XW,
                                                      const float *__restrict__ AS,
                                                      const float *__restrict__ AD,
                                                      const float *__restrict__ bias,
                                                      float *__restrict__ H) {
    int lane = threadIdx.x & 31;
    int node = blockIdx.x * 8 + (threadIdx.x >> 5);
    if (node >= NN) return;
    int start = g_rowp[node], end = g_rowp[node + 1];
    float adst = AD[node];
    float acc0 = 0.f, acc1 = 0.f, acc2 = 0.f, ssum = 0.f, m = -1e30f;

    float cas = 0.f, cx0 = 0.f, cx1 = 0.f, cx2 = 0.f;
    if (start < end) {
        int s = g_csr_src[start];
        cas = AS[s];
        const float *xr = XW + (size_t)s * DH;
        cx0 = xr[lane]; cx1 = xr[lane + 32]; cx2 = xr[lane + 64];
    }
    for (int p = start; p < end; p++) {
        float nas = 0.f, nx0 = 0.f, nx1 = 0.f, nx2 = 0.f;
        if (p + 1 < end) {
            int sn = g_csr_src[p + 1];
            nas = AS[sn];
            const float *xr = XW + (size_t)sn * DH;
            nx0 = xr[lane]; nx1 = xr[lane + 32]; nx2 = xr[lane + 64];
        }
        float l = leakyf(cas + adst);
        float mn = fmaxf(m, l);
        float sc = __expf(m - mn);
        float w = __expf(l - mn);
        acc0 = acc0 * sc + w * cx0;
        acc1 = acc1 * sc + w * cx1;
        acc2 = acc2 * sc + w * cx2;
        ssum = ssum * sc + w;
        m = mn;
        cas = nas; cx0 = nx0; cx1 = nx1; cx2 = nx2;
    }
    float inv = (end > start) ? 1.f / ssum : 0.f;
    float o0 = acc0 * inv + bias[lane];
    float o1 = acc1 * inv + bias[lane + 32];
    float o2 = acc2 * inv + bias[lane + 64];
    float *hg = H + (size_t)node * DH;
    hg[lane] = eluf(o0);
    hg[lane + 32] = eluf(o1);
    hg[lane + 64] = eluf(o2);
}

// ---------------- GRU gates + relu (updates X in place) ----------------------
__device__ __forceinline__ float gru1(float ir, float iz, float inn, float hr,
                                      float hz, float hn, float h) {
    float r = sigmf(ir + hr);
    float z = sigmf(iz + hz);
    float n = tanhfast(inn + r * hn);
    float v = (1.f - z) * n + z * h;
    return fmaxf(v, 0.f);
}

__global__ __launch_bounds__(256) void gru_gate_kernel(const float *__restrict__ GI,
                                                       const float *__restrict__ GH,
                                                       float *__restrict__ X) {
    int idx = blockIdx.x * 256 + threadIdx.x;
    if (idx >= NN * 24) return;
    int node = idx / 24;
    int c = (idx - node * 24) * 4;
    const float *gi = GI + (size_t)node * 288;
    const float *gh = GH + (size_t)node * 288;
    float4 ir = *(const float4 *)(gi + c);
    float4 iz = *(const float4 *)(gi + 96 + c);
    float4 in_ = *(const float4 *)(gi + 192 + c);
    float4 hr = *(const float4 *)(gh + c);
    float4 hz = *(const float4 *)(gh + 96 + c);
    float4 hn = *(const float4 *)(gh + 192 + c);
    float *xp = X + (size_t)node * DH + c;
    float4 xo = *(const float4 *)xp;
    float4 res;
    res.x = gru1(ir.x, iz.x, in_.x, hr.x, hz.x, hn.x, xo.x);
    res.y = gru1(ir.y, iz.y, in_.y, hr.y, hz.y, hn.y, xo.y);
    res.z = gru1(ir.z, iz.z, in_.z, hr.z, hz.z, hn.z, xo.z);
    res.w = gru1(ir.w, iz.w, in_.w, hr.w, hz.w, hn.w, xo.w);
    *(float4 *)xp = res;
}

// ---------------- final layernorm (no affine) --------------------------------
__global__ __launch_bounds__(256) void ln_kernel(const float *__restrict__ X,
                                                 float *__restrict__ out) {
    int lane = threadIdx.x & 31;
    int node = blockIdx.x * 8 + (threadIdx.x >> 5);
    if (node >= NN) return;
    const float *xr = X + (size_t)node * DH;
    float a0 = xr[lane], a1 = xr[lane + 32], a2 = xr[lane + 64];
    float s = a0 + a1 + a2;
#pragma unroll
    for (int off = 16; off > 0; off >>= 1) s += __shfl_xor_sync(0xffffffffu, s, off);
    float mu = s * (1.f / 96.f);
    float d0 = a0 - mu, d1 = a1 - mu, d2 = a2 - mu;
    float ss = d0 * d0 + d1 * d1 + d2 * d2;
#pragma unroll
    for (int off = 16; off > 0; off >>= 1) ss += __shfl_xor_sync(0xffffffffu, ss, off);
    float inv = rsqrtf(ss * (1.f / 96.f) + 1e-5f);
    float *og = out + (size_t)node * DH;
    og[lane] = d0 * inv;
    og[lane + 32] = d1 * inv;
    og[lane + 64] = d2 * inv;
}

// ---------------- launch -----------------------------------------------------
extern "C" void kernel_launch(void* const* d_in, const int* in_sizes, int n_in,
                              void* d_out, int out_size) {
    const float *x = (const float *)d_in[0];
    const void *eidx = (const void *)d_in[1];
    const float *edge_attr = (const float *)d_in[2];
    const float *W_enter = (const float *)d_in[3];
    const float *b_enter = (const float *)d_in[4];
    const float *e_lin1 = (const float *)d_in[5];
    const float *e_lin2 = (const float *)d_in[6];
    const float *e_att_l = (const float *)d_in[7];
    const float *e_att_r = (const float *)d_in[8];
    const float *e_bias = (const float *)d_in[9];
    const float *gat_W = (const float *)d_in[10];
    const float *gat_att_src = (const float *)d_in[11];
    const float *gat_att_dst = (const float *)d_in[12];
    const float *gat_bias = (const float *)d_in[13];
    const float *gru_Wih = (const float *)d_in[14];
    const float *gru_Whh = (const float *)d_in[15];
    const float *gru_bih = (const float *)d_in[16];
    const float *gru_bhh = (const float *)d_in[17];
    float *out = (float *)d_out;

    const int SM96 = (96 * 100 + 128 * 98 + 192) * 4;   // 89344 B
    const int SM64 = (64 * 100 + 128 * 66 + 192) * 4;   // 60160 B
    cudaFuncSetAttribute(mm_kernel<64, ACT_LEAKY, false, true>,
                         cudaFuncAttributeMaxDynamicSharedMemorySize, SM64);
    cudaFuncSetAttribute(mm_kernel<96, ACT_NONE, false, false>,
                         cudaFuncAttributeMaxDynamicSharedMemorySize, SM96);
    cudaFuncSetAttribute(mm_kernel<96, ACT_NONE, false, true>,
                         cudaFuncAttributeMaxDynamicSharedMemorySize, SM96);
    cudaFuncSetAttribute(mm_kernel<96, ACT_ELU, false, false>,
                         cudaFuncAttributeMaxDynamicSharedMemorySize, SM96);
    cudaFuncSetAttribute(mm_kernel<96, ACT_BIAS, true, false>,
                         cudaFuncAttributeMaxDynamicSharedMemorySize, SM96);

    float *pX, *pU, *pAGG, *pH, *pGI, *pGH, *pAD, *pAS;
    cudaGetSymbolAddress((void **)&pX, g_X);
    cudaGetSymbolAddress((void **)&pU, g_U);
    cudaGetSymbolAddress((void **)&pAGG, g_AGG);
    cudaGetSymbolAddress((void **)&pH, g_H);
    cudaGetSymbolAddress((void **)&pGI, g_GI);
    cudaGetSymbolAddress((void **)&pGH, g_GH);
    cudaGetSymbolAddress((void **)&pAD, g_AD);
    cudaGetSymbolAddress((void **)&pAS, g_AS);

    const int EB = (NE + 255) / 256;     // 3125
    const int NB = (NN + 255) / 256;     // 196
    const int WB8 = (NN + 7) / 8;        // warp-per-node kernels, 256 thr
    const int WB4 = (NN + 3) / 4;        // edge0 agg, 128 thr
    const int RB = (NN + 127) / 128;     // 391 GEMM row blocks

    // entry first: X = leaky(x @ W_enter + b_enter), fused AD0 = X @ e_att_r
    mm_kernel<64, ACT_LEAKY, false, true><<<dim3(RB, 1), 256, SM64>>>(
        x, W_enter, b_enter, pX, e_att_r, nullptr, pAD, nullptr, NN, 96);

    // CSR build (independent of entry GEMM)
    k_zero_detect<<<NB, 256>>>(eidx);
    k_extract_hist<<<EB, 256>>>(eidx);
    k_bsum<<<49, 1024>>>();
    k_bscan<<<1, 32>>>();
    k_scan<<<49, 1024>>>();
    k_scatter<<<EB, 256>>>();

    // --- Edge2dConv layer 0 ---
    mm_kernel<96, ACT_NONE, false, false><<<dim3(RB, 1), 256, SM96>>>(
        pX, e_lin1, nullptr, pU, nullptr, nullptr, nullptr, nullptr, NN, 96);
    edge0_agg_kernel<<<WB4, 128>>>(pU, edge_attr, e_lin1 + 96 * 96, e_att_l, pAD,
                                   pAGG);
    mm_kernel<96, ACT_ELU, false, false><<<dim3(RB, 1), 256, SM96>>>(
        pAGG, e_lin2, e_bias, pH, nullptr, nullptr, nullptr, nullptr, NN, 96);
    mm_kernel<96, ACT_BIAS, true, false><<<dim3(RB, 3), 256, SM96>>>(
        pH, gru_Wih, gru_bih, pGI, nullptr, nullptr, nullptr, nullptr, NN, 288);
    mm_kernel<96, ACT_BIAS, true, false><<<dim3(RB, 3), 256, SM96>>>(
        pX, gru_Whh, gru_bhh, pGH, nullptr, nullptr, nullptr, nullptr, NN, 288);
    gru_gate_kernel<<<(NN * 24 + 255) / 256, 256>>>(pGI, pGH, pX);

    // --- GAT layers ---
    for (int l = 0; l < 2; l++) {
        mm_kernel<96, ACT_NONE, false, true><<<dim3(RB, 1), 256, SM96>>>(
            pX, gat_W + (size_t)l * 96 * 96, nullptr, pU, gat_att_src + l * 96,
            gat_att_dst + l * 96, pAS, pAD, NN, 96);
        gat_agg_kernel<<<WB8, 256>>>(pU, pAS, pAD, gat_bias + l * 96, pH);
        mm_kernel<96, ACT_BIAS, true, false><<<dim3(RB, 3), 256, SM96>>>(
            pH, gru_Wih + (size_t)(l + 1) * 288 * 96, gru_bih + (l + 1) * 288, pGI,
            nullptr, nullptr, nullptr, nullptr, NN, 288);
        mm_kernel<96, ACT_BIAS, true, false><<<dim3(RB, 3), 256, SM96>>>(
            pX, gru_Whh + (size_t)(l + 1) * 288 * 96, gru_bhh + (l + 1) * 288, pGH,
            nullptr, nullptr, nullptr, nullptr, NN, 288);
        gru_gate_kernel<<<(NN * 24 + 255) / 256, 256>>>(pGI, pGH, pX);
    }

    ln_kernel<<<WB8, 256>>>(pX, out);
}